// round 11
// baseline (speedup 1.0000x reference)
#include <cuda_runtime.h>
#include <cstdint>

#define FULL 0xffffffffu

constexpr int N = 65536;
constexpr int D = 512;
constexpr int TPB  = 256;                        // 8 warps
constexpr int GRID = 592;                        // 4 CTAs/SM * 148 SMs
constexpr int GW   = GRID * (TPB / 32);          // 4736 warps total

// ---------------------------------------------------------------------------
// Persistent device state (allocation-free). Replay invariants:
//   g_s, g_t, g_maxkey : zeroed in post-barrier windows
//   g_cnt              : self-resetting (last arriver)
//   g_flag             : monotonic, observed at kernel entry
//   g_c, g_part, g_x   : overwrite-before-read each call
// ---------------------------------------------------------------------------
__device__ __align__(16) float g_s[D];
__device__ __align__(16) float g_t[D];
__device__ float    g_c;
__device__ unsigned g_maxkey;
__device__ __align__(16) float g_part[64];
__device__ __align__(16) float g_x[N];
__device__ unsigned g_cnt[4];
__device__ volatile unsigned g_flag[4];

__device__ __forceinline__ float warp_sum(float v) {
#pragma unroll
    for (int o = 16; o; o >>= 1) v += __shfl_xor_sync(FULL, v, o);
    return v;
}
__device__ __forceinline__ float dot4(float4 a, float4 w) {
    return fmaf(a.w, w.w, fmaf(a.z, w.z, fmaf(a.y, w.y, a.x * w.x)));
}

// Grid-wide barrier, graph-replay-safe (design identical to passing R9).
__device__ __forceinline__ void gbar(int i, unsigned f) {
    __syncthreads();
    if (threadIdx.x == 0) {
        __threadfence();
        unsigned pos = atomicAdd(&g_cnt[i], 1u);
        if (pos == GRID - 1) {
            g_cnt[i] = 0;
            __threadfence();
            g_flag[i] = f + 1;
        } else {
            while (g_flag[i] == f) { __nanosleep(64); }
        }
        __threadfence();
    }
    __syncthreads();
}

// ---------------------------------------------------------------------------
// Fused persistent kernel. One row per warp-iteration keeps live registers
// ~50 so the __launch_bounds__(256,4) contract is met without spills.
// ---------------------------------------------------------------------------
__global__ void __launch_bounds__(TPB, 4)
fused(const float* __restrict__ inp, const float* __restrict__ kw,
      const float* __restrict__ kb,  const float* __restrict__ vw,
      const float* __restrict__ vb,  float* __restrict__ out) {
    __shared__ __align__(16) float s_wt[D];      // key_w in phase A, t in phase C
    __shared__ float s_red[D];
    __shared__ float s_p[8];

    const int tid  = threadIdx.x;
    const int lane = tid & 31;
    const int bid  = blockIdx.x;
    const int gw   = (bid * TPB + tid) >> 5;

    unsigned f0 = 0, f1 = 0, f2 = 0, f3 = 0;
    if (tid == 0) { f0 = g_flag[0]; f1 = g_flag[1]; f2 = g_flag[2]; f3 = g_flag[3]; }

    s_wt[tid] = kw[tid]; s_wt[tid + 256] = kw[tid + 256];
    s_red[tid] = 0.0f;   s_red[tid + 256] = 0.0f;
    __syncthreads();

    const float kb0 = kb[0];
    const float4* __restrict__ sw4  = (const float4*)s_wt;
    const float4* __restrict__ inp4 = (const float4*)inp;

    // ---------------- Phase A: s = sum_n inputs[n] * k[n], ASCENDING -------
    {
        float4 s0 = {0,0,0,0}, s1 = {0,0,0,0}, s2 = {0,0,0,0}, s3 = {0,0,0,0};
        for (int r = gw; r < N; r += GW) {
            const float4* __restrict__ row = inp4 + (size_t)r * (D / 4);
            const float4 a0 = row[lane],      a1 = row[lane + 32],
                         a2 = row[lane + 64], a3 = row[lane + 96];

            float4 w = sw4[lane];
            float d = dot4(a0, w);
            w = sw4[lane + 32]; d += dot4(a1, w);
            w = sw4[lane + 64]; d += dot4(a2, w);
            w = sw4[lane + 96]; d += dot4(a3, w);
            d = warp_sum(d);
            const float kv = d + kb0;

            s0.x = fmaf(a0.x, kv, s0.x); s0.y = fmaf(a0.y, kv, s0.y);
            s0.z = fmaf(a0.z, kv, s0.z); s0.w = fmaf(a0.w, kv, s0.w);
            s1.x = fmaf(a1.x, kv, s1.x); s1.y = fmaf(a1.y, kv, s1.y);
            s1.z = fmaf(a1.z, kv, s1.z); s1.w = fmaf(a1.w, kv, s1.w);
            s2.x = fmaf(a2.x, kv, s2.x); s2.y = fmaf(a2.y, kv, s2.y);
            s2.z = fmaf(a2.z, kv, s2.z); s2.w = fmaf(a2.w, kv, s2.w);
            s3.x = fmaf(a3.x, kv, s3.x); s3.y = fmaf(a3.y, kv, s3.y);
            s3.z = fmaf(a3.z, kv, s3.z); s3.w = fmaf(a3.w, kv, s3.w);
        }
        const int b0i = 4 * lane;
        atomicAdd(&s_red[b0i + 0],       s0.x); atomicAdd(&s_red[b0i + 1],       s0.y);
        atomicAdd(&s_red[b0i + 2],       s0.z); atomicAdd(&s_red[b0i + 3],       s0.w);
        atomicAdd(&s_red[128 + b0i + 0], s1.x); atomicAdd(&s_red[128 + b0i + 1], s1.y);
        atomicAdd(&s_red[128 + b0i + 2], s1.z); atomicAdd(&s_red[128 + b0i + 3], s1.w);
        atomicAdd(&s_red[256 + b0i + 0], s2.x); atomicAdd(&s_red[256 + b0i + 1], s2.y);
        atomicAdd(&s_red[256 + b0i + 2], s2.z); atomicAdd(&s_red[256 + b0i + 3], s2.w);
        atomicAdd(&s_red[384 + b0i + 0], s3.x); atomicAdd(&s_red[384 + b0i + 1], s3.y);
        atomicAdd(&s_red[384 + b0i + 2], s3.z); atomicAdd(&s_red[384 + b0i + 3], s3.w);
        __syncthreads();
        atomicAdd(&g_s[tid], s_red[tid]);
        atomicAdd(&g_s[tid + 256], s_red[tid + 256]);
    }

    gbar(0, f0);   // s complete

    // ---------------- Phase B: t = vw^T s (64 CTAs), c = vb.s (CTA 64) -----
    if (bid < 64) {
        const int jb = bid >> 1;                  // 32 j-blocks of 16
        const int d  = (bid & 1) * 256 + tid;     // 256 d's per CTA
        const int j0 = jb * 16;
        float acc = 0.0f;
#pragma unroll
        for (int j = 0; j < 16; j++)
            acc = fmaf(vw[(size_t)(j0 + j) * D + d], g_s[j0 + j], acc);
        atomicAdd(&g_t[d], acc);
    } else if (bid == 64) {
        float v = vb[tid] * g_s[tid] + vb[tid + 256] * g_s[tid + 256];
        v = warp_sum(v);
        if (lane == 0) s_p[tid >> 5] = v;
        __syncthreads();
        if (tid < 32) {
            float s = (lane < 8) ? s_p[lane] : 0.0f;
            s = warp_sum(s);
            if (lane == 0) g_c = s;
        }
    }

    gbar(1, f1);   // t and c complete

    if (bid == 0) { g_s[tid] = 0.0f; g_s[tid + 256] = 0.0f; }   // replay reset

    // stage t into smem (overwrites key_w — phase A done)
    s_wt[tid] = g_t[tid]; s_wt[tid + 256] = g_t[tid + 256];
    __syncthreads();
    const float c = g_c;

    // ---------------- Phase C: x = inputs . t + c, DESCENDING (L2 ping-pong)
    {
        float maxv = -3.4e38f;
        for (int r = N - 1 - gw; r >= 0; r -= GW) {
            const float4* __restrict__ row = inp4 + (size_t)r * (D / 4);
            const float4 a0 = row[lane],      a1 = row[lane + 32],
                         a2 = row[lane + 64], a3 = row[lane + 96];

            float4 w = sw4[lane];
            float d = dot4(a0, w);
            w = sw4[lane + 32]; d += dot4(a1, w);
            w = sw4[lane + 64]; d += dot4(a2, w);
            w = sw4[lane + 96]; d += dot4(a3, w);
            d = warp_sum(d);

            const float x = d + c;
            if (lane == 0) g_x[r] = x;
            maxv = fmaxf(maxv, x);
        }
        if (lane == 0) {
            unsigned u = __float_as_uint(maxv);
            unsigned key = (u & 0x80000000u) ? ~u : (u | 0x80000000u);
            atomicMax(&g_maxkey, key);
        }
    }

    gbar(2, f2);   // x and max complete

    if (bid == 1) { g_t[tid] = 0.0f; g_t[tid + 256] = 0.0f; }   // replay reset

    // ---------------- Phase D1: e = exp(x - max) (64 CTAs), block partials -
    if (bid < 64) {
        const unsigned key = g_maxkey;
        const unsigned ub = (key & 0x80000000u) ? (key & 0x7fffffffu) : ~key;
        const float gmax = __uint_as_float(ub);

        const int g = bid * TPB + tid;           // < 16384 float4 elems
        const float4 v = ((const float4*)g_x)[g];
        float4 e;
        e.x = expf(v.x - gmax); e.y = expf(v.y - gmax);
        e.z = expf(v.z - gmax); e.w = expf(v.w - gmax);
        ((float4*)g_x)[g] = e;

        float ws = warp_sum((e.x + e.y) + (e.z + e.w));
        if (lane == 0) s_p[tid >> 5] = ws;
        __syncthreads();
        if (tid < 32) {
            float s = (lane < 8) ? s_p[lane] : 0.0f;
            s = warp_sum(s);
            if (lane == 0) g_part[bid] = s;
        }
    }

    gbar(3, f3);   // e and partials complete

    if (bid == 2 && tid == 0) g_maxkey = 0u;     // replay reset

    // ---------------- Phase D2: out = e / sumexp ---------------------------
    if (bid < 64) {
        const float4* __restrict__ pp = (const float4*)g_part;
        float sum = 0.0f;
#pragma unroll
        for (int i = 0; i < 16; i++) {
            const float4 q = pp[i];
            sum += (q.x + q.y) + (q.z + q.w);
        }
        const float inv = 1.0f / sum;
        const int g = bid * TPB + tid;
        const float4 e = ((const float4*)g_x)[g];
        float4 r;
        r.x = e.x * inv; r.y = e.y * inv; r.z = e.z * inv; r.w = e.w * inv;
        ((float4*)out)[g] = r;
    }
}

// ---------------------------------------------------------------------------
extern "C" void kernel_launch(void* const* d_in, const int* in_sizes, int n_in,
                              void* d_out, int out_size) {
    (void)in_sizes; (void)n_in; (void)out_size;
    const float* inp = (const float*)d_in[0];   // [N, D]
    const float* kw  = (const float*)d_in[1];   // [1, D]
    const float* kb  = (const float*)d_in[2];   // [1]
    const float* vw  = (const float*)d_in[3];   // [D, D]
    const float* vb  = (const float*)d_in[4];   // [D]
    float* out = (float*)d_out;                 // [N, 1]

    fused<<<GRID, TPB>>>(inp, kw, kb, vw, vb, out);
}